// round 16
// baseline (speedup 1.0000x reference)
#include <cuda_runtime.h>
#include <cuda_fp16.h>
#include <cstdint>
#include <cstddef>

#define N_NODES_MAX 100000
#define D_FEAT 128
#define HIDDEN 64
#define SA 136   // smem/global W row stride in fp16 units (272 B)

// fp16 node table: C[n][0:64] = emb@w1_top + b1 ; C[n][64:128] = emb@w1_bot
__device__ __align__(16) __half g_C[(size_t)N_NODES_MAX * 128];
// Pre-converted W (fp16), [128 n][SA k] — exact smem image
__device__ __align__(16) __half g_W[128 * SA];

// ===========================================================================
// PTX helpers (sm_80-era; compile under plain sm_100 target)
// ===========================================================================
__device__ __forceinline__ uint32_t smem_u32(const void* p) {
    uint32_t a;
    asm("{ .reg .u64 t; cvta.to.shared.u64 t, %1; cvt.u32.u64 %0, t; }"
        : "=r"(a) : "l"(p));
    return a;
}
__device__ __forceinline__ void ldsm_x4(uint32_t* r, uint32_t addr) {
    asm volatile("ldmatrix.sync.aligned.m8n8.x4.shared.b16 {%0,%1,%2,%3}, [%4];"
                 : "=r"(r[0]), "=r"(r[1]), "=r"(r[2]), "=r"(r[3]) : "r"(addr));
}
__device__ __forceinline__ void ldsm_x2(uint32_t* r, uint32_t addr) {
    asm volatile("ldmatrix.sync.aligned.m8n8.x2.shared.b16 {%0,%1}, [%2];"
                 : "=r"(r[0]), "=r"(r[1]) : "r"(addr));
}
__device__ __forceinline__ void mma_fp16(float* c, const uint32_t* a, const uint32_t* b) {
    asm volatile("mma.sync.aligned.m16n8k16.row.col.f32.f16.f16.f32 "
                 "{%0,%1,%2,%3}, {%4,%5,%6,%7}, {%8,%9}, {%0,%1,%2,%3};"
                 : "+f"(c[0]), "+f"(c[1]), "+f"(c[2]), "+f"(c[3])
                 : "r"(a[0]), "r"(a[1]), "r"(a[2]), "r"(a[3]),
                   "r"(b[0]), "r"(b[1]));
}
__device__ __forceinline__ void cp_async16(uint32_t dst, const void* src) {
    asm volatile("cp.async.cg.shared.global [%0], [%1], 16;"
                 :: "r"(dst), "l"(src) : "memory");
}
__device__ __forceinline__ uint32_t packh2(float x, float y) {
    __half2 t = __floats2half2_rn(x, y);
    return *(uint32_t*)&t;
}

// ===========================================================================
// Kernel 0: convert w1 -> g_W (fp16), layout [n][k], k contiguous.
//   W[n][k] = n<64 ? w1[k*64+n] : w1[(128+k)*64 + (n-64)]
// ===========================================================================
__global__ void setup_w_kernel(const float* __restrict__ w1)
{
    int idx = blockIdx.x * blockDim.x + threadIdx.x;   // 0..8191
    if (idx >= 128 * 64) return;
    int n  = idx >> 6;            // 0..127
    int k2 = (idx & 63) * 2;      // 0..126
    int base = (n < 64) ? 0 : 128;
    int nn   = (n < 64) ? n : (n - 64);
    float v0 = w1[(size_t)(base + k2)     * HIDDEN + nn];
    float v1 = w1[(size_t)(base + k2 + 1) * HIDDEN + nn];
    *(uint32_t*)&g_W[n * SA + k2] = packh2(v0, v1);
}

// ===========================================================================
// Kernel 1: C (M x 128) = A (M x 128) @ W (128 x 128), single fp16 mma.sync
// (fp32 accumulate) -> +b1 (cols<64) -> smem -> coalesced fp16 store.
// CTA: BM=64, 256 threads = 8 warps (2x4), warp tile m32 x n32, full K=128.
// [R11 known-good]
// ===========================================================================
#define SM_AH 0
#define SM_WH 17408
#define SM_B1 52224
#define SMEM_GEMM_TOTAL (SM_B1 + 64 * 4)

__global__ __launch_bounds__(256, 3)
void precompute_kernel(const float* __restrict__ A,
                       const float* __restrict__ b1,
                       int M)
{
    extern __shared__ char smem[];
    const uint32_t sb  = smem_u32(smem);
    const int tid  = threadIdx.x;
    const int wid  = tid >> 5;
    const int lane = tid & 31;
    const int bm   = blockIdx.x * 64;

    // ---- W: flat async copy of the pre-built fp16 image (34,816 B) ----
    {
        const uint4* src = (const uint4*)g_W;
#pragma unroll
        for (int i = 0; i < 9; i++) {
            int v = tid + i * 256;               // 0..2303
            if (v < 2176) cp_async16(sb + SM_WH + v * 16, src + v);
        }
        asm volatile("cp.async.commit_group;" ::: "memory");
    }

    float* b1s = (float*)(smem + SM_B1);
    if (tid < 64) b1s[tid] = b1[tid];

    // ---- A tile: 64 rows x 128 cols f32 -> fp16 ----
#pragma unroll
    for (int i = 0; i < 8; i++) {
        int idx4 = tid + i * 256;                // 0..2047
        int row  = idx4 >> 5;                    // 0..63
        int col  = (idx4 & 31) * 4;              // 0..124
        int gr   = bm + row; if (gr >= M) gr = M - 1;
        float4 v = *(const float4*)(A + (size_t)gr * D_FEAT + col);
        uint32_t off = ((uint32_t)row * SA + col) * 2;
        *(uint32_t*)(smem + SM_AH + off)     = packh2(v.x, v.y);
        *(uint32_t*)(smem + SM_AH + off + 4) = packh2(v.z, v.w);
    }
    asm volatile("cp.async.wait_group 0;" ::: "memory");
    __syncthreads();

    // ---- Warp tiles: 2 (m) x 4 (n); each warp m32 x n32 ----
    const int wm = wid >> 2;            // 0..1
    const int wn = wid & 3;             // 0..3
    const int m_base = wm * 32;
    const int n_base = wn * 32;

    const int rA  = (lane & 7) + ((lane >> 3) & 1) * 8;
    const int kA8 = ((lane >> 4) & 1) * 8;
    const uint32_t aoff = ((uint32_t)(m_base + rA) * SA + kA8) * 2;
    const int rB  = lane & 7;
    const int kB8 = ((lane >> 3) & 1) * 8;
    const uint32_t boff = ((uint32_t)(n_base + rB) * SA + kB8) * 2;

    float acc[2][4][4];
#pragma unroll
    for (int mt = 0; mt < 2; mt++)
#pragma unroll
        for (int nt = 0; nt < 4; nt++)
#pragma unroll
            for (int r = 0; r < 4; r++) acc[mt][nt][r] = 0.f;

#pragma unroll
    for (int s = 0; s < 8; s++) {
        const uint32_t k0b = (uint32_t)(s * 16) * 2;
        uint32_t ah[2][4], bh[4][2];
#pragma unroll
        for (int mt = 0; mt < 2; mt++)
            ldsm_x4(ah[mt], sb + SM_AH + aoff + (uint32_t)(mt * 16 * SA) * 2 + k0b);
#pragma unroll
        for (int nt = 0; nt < 4; nt++)
            ldsm_x2(bh[nt], sb + SM_WH + boff + (uint32_t)(nt * 8 * SA) * 2 + k0b);
#pragma unroll
        for (int mt = 0; mt < 2; mt++)
#pragma unroll
            for (int nt = 0; nt < 4; nt++)
                mma_fp16(acc[mt][nt], ah[mt], bh[nt]);
    }

    // ---- Epilogue pass 1: +bias, fp16, STS into the A buffer (conflict-free) ----
    __syncthreads();   // all warps done reading SM_AH via ldmatrix
    const int er = lane >> 2;
    const int ec = (lane & 3) * 2;
#pragma unroll
    for (int mt = 0; mt < 2; mt++) {
#pragma unroll
        for (int half = 0; half < 2; half++) {
            int lrow = m_base + mt * 16 + er + half * 8;   // 0..63
#pragma unroll
            for (int nt = 0; nt < 4; nt++) {
                int col = n_base + nt * 8 + ec;
                float x = acc[mt][nt][half * 2 + 0];
                float y = acc[mt][nt][half * 2 + 1];
                if (col < 64) { x += b1s[col]; y += b1s[col + 1]; }
                *(uint32_t*)(smem + SM_AH + ((uint32_t)lrow * SA + col) * 2) = packh2(x, y);
            }
        }
    }
    __syncthreads();

    // ---- Epilogue pass 2: coalesced STG.128 (2 rows x 256 B per warp-store) ----
#pragma unroll
    for (int i = 0; i < 4; i++) {
        int v   = tid + i * 256;         // 0..1023
        int row = v >> 4;                // 0..63
        int c16 = v & 15;                // 16 uint4 per 128-half row
        int gm  = bm + row;
        if (gm < M) {
            *(uint4*)(g_C + (size_t)gm * 128 + c16 * 8) =
                *(const uint4*)(smem + SM_AH + ((uint32_t)row * SA + c16 * 8) * 2);
        }
    }
}

// ===========================================================================
// Kernel 2: PERSISTENT per-edge readout. 592 resident blocks loop over
// 128-edge chunks with double-buffered index staging: chunk-i gathers
// overlap chunk-(i+1) index loads. 8 threads/edge, 4 edges/group.
// out[e] = sum_j relu(C[s][j] + C[d][64+j]) * w2[j]
// ===========================================================================
__global__ __launch_bounds__(256)
void edge_kernel(const unsigned int* __restrict__ ts_raw,
                 const float* __restrict__ w2,
                 float* __restrict__ out, int E, int M, int nchunks)
{
    __shared__ float w2s[HIDDEN];
    __shared__ unsigned int sidx[2][128], didx[2][128];
    __shared__ int is64s;

    const int tid = threadIdx.x;
    if (tid < HIDDEN) w2s[tid] = w2[tid];
    if (tid == 0) {
        // int64 indices < 2^17 => every odd u32 word is 0 (little-endian)
        unsigned int acc = 0;
#pragma unroll
        for (int i = 1; i < 32; i += 2) acc |= ts_raw[i];
        is64s = (acc == 0) ? 1 : 0;
    }
    __syncthreads();
    const int is64 = is64s;

    // staging role: threads 0-127 load src of edge (tid&127); 128-255 load dst
    const int se   = tid & 127;
    const int ldst = tid >> 7;          // 0 = src, 1 = dst

    auto stage = [&](int k, int b) {
        int e = k * 128 + se;
        unsigned int v = 0;
        if (e < E) {
            if (is64) v = ts_raw[4 * (size_t)e + 2 * ldst];
            else      v = ts_raw[2 * (size_t)e + ldst];
        }
        if (v >= (unsigned)M) v = 0;
        if (ldst == 0) sidx[b][se] = v; else didx[b][se] = v;
    };

    const int sub = tid & 7;
    const int grp = tid >> 3;           // 0..31

    float4 w0 = ((const float4*)w2s)[sub * 2];
    float4 w1v = ((const float4*)w2s)[sub * 2 + 1];
    const float wv[8] = {w0.x, w0.y, w0.z, w0.w, w1v.x, w1v.y, w1v.z, w1v.w};

    int k = blockIdx.x;
    if (k >= nchunks) return;
    stage(k, 0);

    int buf = 0;
    for (; k < nchunks; k += gridDim.x) {
        __syncthreads();                // staged indices for buf visible

        // ---- issue 8 gathers for this chunk (indices via LDS broadcast) ----
        uint4 p[4], q[4];
#pragma unroll
        for (int j = 0; j < 4; j++) {
            int le = grp + 32 * j;
            unsigned int s = sidx[buf][le];
            unsigned int d = didx[buf][le];
            p[j] = *((const uint4*)(g_C + (size_t)s * 128) + sub);
            q[j] = *((const uint4*)(g_C + (size_t)d * 128 + 64) + sub);
        }

        // ---- stage next chunk's indices (overlaps gather latency) ----
        int kn = k + gridDim.x;
        if (kn < nchunks) stage(kn, buf ^ 1);

        // ---- compute + reduce + store ----
        float acc[4] = {0.f, 0.f, 0.f, 0.f};
#pragma unroll
        for (int j = 0; j < 4; j++) {
            const __half2* ph = (const __half2*)&p[j];
            const __half2* qh = (const __half2*)&q[j];
#pragma unroll
            for (int i = 0; i < 4; i++) {
                float2 a = __half22float2(ph[i]);
                float2 b = __half22float2(qh[i]);
                acc[j] = fmaf(fmaxf(a.x + b.x, 0.f), wv[i * 2 + 0], acc[j]);
                acc[j] = fmaf(fmaxf(a.y + b.y, 0.f), wv[i * 2 + 1], acc[j]);
            }
        }
#pragma unroll
        for (int off = 4; off >= 1; off >>= 1)
#pragma unroll
            for (int j = 0; j < 4; j++)
                acc[j] += __shfl_down_sync(0xffffffffu, acc[j], off, 8);

        if (sub == 0) {
#pragma unroll
            for (int j = 0; j < 4; j++) {
                int e = k * 128 + grp + 32 * j;
                if (e < E) out[e] = acc[j];
            }
        }
        buf ^= 1;
    }
}

// ===========================================================================
extern "C" void kernel_launch(void* const* d_in, const int* in_sizes, int n_in,
                              void* d_out, int out_size)
{
    const float*        emb = (const float*)d_in[0];
    const unsigned int* ts  = (const unsigned int*)d_in[1];
    const float*        w1  = (const float*)d_in[2];
    const float*        b1  = (const float*)d_in[3];
    const float*        w2  = (const float*)d_in[4];
    float*              out = (float*)d_out;

    int M = in_sizes[0] / D_FEAT;
    int E = in_sizes[1] / 2;

    int nchunks = (E + 127) / 128;
    int egrid = 592;                       // 4 blocks/SM, single wave
    if (egrid > nchunks) egrid = nchunks;

    setup_w_kernel<<<32, 256>>>(w1);
    cudaFuncSetAttribute(precompute_kernel,
                         cudaFuncAttributeMaxDynamicSharedMemorySize, SMEM_GEMM_TOTAL);
    precompute_kernel<<<(M + 63) / 64, 256, SMEM_GEMM_TOTAL>>>(emb, b1, M);
    edge_kernel<<<egrid, 256>>>(ts, w2, out, E, M, nchunks);
}

// round 17
// speedup vs baseline: 1.0522x; 1.0522x over previous
#include <cuda_runtime.h>
#include <cuda_fp16.h>
#include <cstdint>
#include <cstddef>

#define N_NODES_MAX 100000
#define D_FEAT 128
#define HIDDEN 64
#define SA 136   // smem/global W row stride in fp16 units (272 B)

// fp16 node table: C[n][0:64] = emb@w1_top + b1 ; C[n][64:128] = emb@w1_bot
__device__ __align__(16) __half g_C[(size_t)N_NODES_MAX * 128];
// Pre-converted W (fp16), [128 n][SA k] — exact smem image
__device__ __align__(16) __half g_W[128 * SA];

// ===========================================================================
// PTX helpers (sm_80-era; compile under plain sm_100 target)
// ===========================================================================
__device__ __forceinline__ uint32_t smem_u32(const void* p) {
    uint32_t a;
    asm("{ .reg .u64 t; cvta.to.shared.u64 t, %1; cvt.u32.u64 %0, t; }"
        : "=r"(a) : "l"(p));
    return a;
}
__device__ __forceinline__ void ldsm_x4(uint32_t* r, uint32_t addr) {
    asm volatile("ldmatrix.sync.aligned.m8n8.x4.shared.b16 {%0,%1,%2,%3}, [%4];"
                 : "=r"(r[0]), "=r"(r[1]), "=r"(r[2]), "=r"(r[3]) : "r"(addr));
}
__device__ __forceinline__ void ldsm_x2(uint32_t* r, uint32_t addr) {
    asm volatile("ldmatrix.sync.aligned.m8n8.x2.shared.b16 {%0,%1}, [%2];"
                 : "=r"(r[0]), "=r"(r[1]) : "r"(addr));
}
__device__ __forceinline__ void mma_fp16(float* c, const uint32_t* a, const uint32_t* b) {
    asm volatile("mma.sync.aligned.m16n8k16.row.col.f32.f16.f16.f32 "
                 "{%0,%1,%2,%3}, {%4,%5,%6,%7}, {%8,%9}, {%0,%1,%2,%3};"
                 : "+f"(c[0]), "+f"(c[1]), "+f"(c[2]), "+f"(c[3])
                 : "r"(a[0]), "r"(a[1]), "r"(a[2]), "r"(a[3]),
                   "r"(b[0]), "r"(b[1]));
}
__device__ __forceinline__ void cp_async16(uint32_t dst, const void* src) {
    asm volatile("cp.async.cg.shared.global [%0], [%1], 16;"
                 :: "r"(dst), "l"(src) : "memory");
}
__device__ __forceinline__ uint32_t packh2(float x, float y) {
    __half2 t = __floats2half2_rn(x, y);
    return *(uint32_t*)&t;
}
// PDL intrinsics via PTX (sm_90+; compiles under compute_100)
__device__ __forceinline__ void pdl_trigger() {
    asm volatile("griddepcontrol.launch_dependents;" ::: "memory");
}
__device__ __forceinline__ void pdl_wait() {
    asm volatile("griddepcontrol.wait;" ::: "memory");
}

// ===========================================================================
// Kernel 0: convert w1 -> g_W (fp16), layout [n][k], k contiguous.
//   W[n][k] = n<64 ? w1[k*64+n] : w1[(128+k)*64 + (n-64)]
// ===========================================================================
__global__ void setup_w_kernel(const float* __restrict__ w1)
{
    int idx = blockIdx.x * blockDim.x + threadIdx.x;   // 0..8191
    if (idx < 128 * 64) {
        int n  = idx >> 6;            // 0..127
        int k2 = (idx & 63) * 2;      // 0..126
        int base = (n < 64) ? 0 : 128;
        int nn   = (n < 64) ? n : (n - 64);
        float v0 = w1[(size_t)(base + k2)     * HIDDEN + nn];
        float v1 = w1[(size_t)(base + k2 + 1) * HIDDEN + nn];
        *(uint32_t*)&g_W[n * SA + k2] = packh2(v0, v1);
    }
    pdl_trigger();   // g_W stores are complete for this thread; dependents may launch
}

// ===========================================================================
// Kernel 1: C (M x 128) = A (M x 128) @ W (128 x 128), single fp16 mma.sync
// (fp32 accumulate) -> +b1 (cols<64) -> smem -> coalesced fp16 store.
// PDL: A staging first (independent of g_W), then griddepcontrol.wait,
// then the W cp.async — overlaps setup_w with the A-load latency.
// CTA: BM=64, 256 threads = 8 warps (2x4), warp tile m32 x n32, full K=128.
// ===========================================================================
#define SM_AH 0
#define SM_WH 17408
#define SM_B1 52224
#define SMEM_GEMM_TOTAL (SM_B1 + 64 * 4)

__global__ __launch_bounds__(256, 3)
void precompute_kernel(const float* __restrict__ A,
                       const float* __restrict__ b1,
                       int M)
{
    extern __shared__ char smem[];
    const uint32_t sb  = smem_u32(smem);
    const int tid  = threadIdx.x;
    const int wid  = tid >> 5;
    const int lane = tid & 31;
    const int bm   = blockIdx.x * 64;

    float* b1s = (float*)(smem + SM_B1);
    if (tid < 64) b1s[tid] = b1[tid];

    // ---- A tile: 64 rows x 128 cols f32 -> fp16 (independent of setup_w) ----
#pragma unroll
    for (int i = 0; i < 8; i++) {
        int idx4 = tid + i * 256;                // 0..2047
        int row  = idx4 >> 5;                    // 0..63
        int col  = (idx4 & 31) * 4;              // 0..124
        int gr   = bm + row; if (gr >= M) gr = M - 1;
        float4 v = *(const float4*)(A + (size_t)gr * D_FEAT + col);
        uint32_t off = ((uint32_t)row * SA + col) * 2;
        *(uint32_t*)(smem + SM_AH + off)     = packh2(v.x, v.y);
        *(uint32_t*)(smem + SM_AH + off + 4) = packh2(v.z, v.w);
    }

    // ---- wait for setup_w, then flat async copy of g_W (34,816 B) ----
    pdl_wait();
    {
        const uint4* src = (const uint4*)g_W;
#pragma unroll
        for (int i = 0; i < 9; i++) {
            int v = tid + i * 256;               // 0..2303
            if (v < 2176) cp_async16(sb + SM_WH + v * 16, src + v);
        }
        asm volatile("cp.async.commit_group;" ::: "memory");
        asm volatile("cp.async.wait_group 0;" ::: "memory");
    }
    __syncthreads();

    // ---- Warp tiles: 2 (m) x 4 (n); each warp m32 x n32 ----
    const int wm = wid >> 2;            // 0..1
    const int wn = wid & 3;             // 0..3
    const int m_base = wm * 32;
    const int n_base = wn * 32;

    const int rA  = (lane & 7) + ((lane >> 3) & 1) * 8;
    const int kA8 = ((lane >> 4) & 1) * 8;
    const uint32_t aoff = ((uint32_t)(m_base + rA) * SA + kA8) * 2;
    const int rB  = lane & 7;
    const int kB8 = ((lane >> 3) & 1) * 8;
    const uint32_t boff = ((uint32_t)(n_base + rB) * SA + kB8) * 2;

    float acc[2][4][4];
#pragma unroll
    for (int mt = 0; mt < 2; mt++)
#pragma unroll
        for (int nt = 0; nt < 4; nt++)
#pragma unroll
            for (int r = 0; r < 4; r++) acc[mt][nt][r] = 0.f;

#pragma unroll
    for (int s = 0; s < 8; s++) {
        const uint32_t k0b = (uint32_t)(s * 16) * 2;
        uint32_t ah[2][4], bh[4][2];
#pragma unroll
        for (int mt = 0; mt < 2; mt++)
            ldsm_x4(ah[mt], sb + SM_AH + aoff + (uint32_t)(mt * 16 * SA) * 2 + k0b);
#pragma unroll
        for (int nt = 0; nt < 4; nt++)
            ldsm_x2(bh[nt], sb + SM_WH + boff + (uint32_t)(nt * 8 * SA) * 2 + k0b);
#pragma unroll
        for (int mt = 0; mt < 2; mt++)
#pragma unroll
            for (int nt = 0; nt < 4; nt++)
                mma_fp16(acc[mt][nt], ah[mt], bh[nt]);
    }

    // ---- Epilogue pass 1: +bias, fp16, STS into the A buffer (conflict-free) ----
    __syncthreads();   // all warps done reading SM_AH via ldmatrix
    const int er = lane >> 2;
    const int ec = (lane & 3) * 2;
#pragma unroll
    for (int mt = 0; mt < 2; mt++) {
#pragma unroll
        for (int half = 0; half < 2; half++) {
            int lrow = m_base + mt * 16 + er + half * 8;   // 0..63
#pragma unroll
            for (int nt = 0; nt < 4; nt++) {
                int col = n_base + nt * 8 + ec;
                float x = acc[mt][nt][half * 2 + 0];
                float y = acc[mt][nt][half * 2 + 1];
                if (col < 64) { x += b1s[col]; y += b1s[col + 1]; }
                *(uint32_t*)(smem + SM_AH + ((uint32_t)lrow * SA + col) * 2) = packh2(x, y);
            }
        }
    }
    __syncthreads();

    // ---- Epilogue pass 2: coalesced STG.128 (2 rows x 256 B per warp-store) ----
#pragma unroll
    for (int i = 0; i < 4; i++) {
        int v   = tid + i * 256;         // 0..1023
        int row = v >> 4;                // 0..63
        int c16 = v & 15;                // 16 uint4 per 128-half row
        int gm  = bm + row;
        if (gm < M) {
            *(uint4*)(g_C + (size_t)gm * 128 + c16 * 8) =
                *(const uint4*)(smem + SM_AH + ((uint32_t)row * SA + c16 * 8) * 2);
        }
    }
}

// ===========================================================================
// Kernel 2: PERSISTENT per-edge readout (592 blocks), double-buffered index
// staging. PDL: stage first chunk's indices + w2 BEFORE griddepcontrol.wait
// (they don't touch g_C), then gather.
// out[e] = sum_j relu(C[s][j] + C[d][64+j]) * w2[j]
// ===========================================================================
__global__ __launch_bounds__(256)
void edge_kernel(const unsigned int* __restrict__ ts_raw,
                 const float* __restrict__ w2,
                 float* __restrict__ out, int E, int M, int nchunks)
{
    __shared__ float w2s[HIDDEN];
    __shared__ unsigned int sidx[2][128], didx[2][128];
    __shared__ int is64s;

    const int tid = threadIdx.x;
    if (tid < HIDDEN) w2s[tid] = w2[tid];
    if (tid == 0) {
        // int64 indices < 2^17 => every odd u32 word is 0 (little-endian)
        unsigned int acc = 0;
#pragma unroll
        for (int i = 1; i < 32; i += 2) acc |= ts_raw[i];
        is64s = (acc == 0) ? 1 : 0;
    }
    __syncthreads();
    const int is64 = is64s;

    // staging role: threads 0-127 load src of edge (tid&127); 128-255 load dst
    const int se   = tid & 127;
    const int ldst = tid >> 7;          // 0 = src, 1 = dst

    auto stage = [&](int k, int b) {
        int e = k * 128 + se;
        unsigned int v = 0;
        if (e < E) {
            if (is64) v = ts_raw[4 * (size_t)e + 2 * ldst];
            else      v = ts_raw[2 * (size_t)e + ldst];
        }
        if (v >= (unsigned)M) v = 0;
        if (ldst == 0) sidx[b][se] = v; else didx[b][se] = v;
    };

    const int sub = tid & 7;
    const int grp = tid >> 3;           // 0..31

    float4 w0 = ((const float4*)w2s)[sub * 2];
    float4 w1v = ((const float4*)w2s)[sub * 2 + 1];
    const float wv[8] = {w0.x, w0.y, w0.z, w0.w, w1v.x, w1v.y, w1v.z, w1v.w};

    int k = blockIdx.x;
    if (k >= nchunks) { pdl_wait(); return; }
    stage(k, 0);

    pdl_wait();     // g_C must be complete before the first gather

    int buf = 0;
    for (; k < nchunks; k += gridDim.x) {
        __syncthreads();                // staged indices for buf visible

        // ---- issue 8 gathers for this chunk (indices via LDS broadcast) ----
        uint4 p[4], q[4];
#pragma unroll
        for (int j = 0; j < 4; j++) {
            int le = grp + 32 * j;
            unsigned int s = sidx[buf][le];
            unsigned int d = didx[buf][le];
            p[j] = *((const uint4*)(g_C + (size_t)s * 128) + sub);
            q[j] = *((const uint4*)(g_C + (size_t)d * 128 + 64) + sub);
        }

        // ---- stage next chunk's indices (overlaps gather latency) ----
        int kn = k + gridDim.x;
        if (kn < nchunks) stage(kn, buf ^ 1);

        // ---- compute + reduce + store ----
        float acc[4] = {0.f, 0.f, 0.f, 0.f};
#pragma unroll
        for (int j = 0; j < 4; j++) {
            const __half2* ph = (const __half2*)&p[j];
            const __half2* qh = (const __half2*)&q[j];
#pragma unroll
            for (int i = 0; i < 4; i++) {
                float2 a = __half22float2(ph[i]);
                float2 b = __half22float2(qh[i]);
                acc[j] = fmaf(fmaxf(a.x + b.x, 0.f), wv[i * 2 + 0], acc[j]);
                acc[j] = fmaf(fmaxf(a.y + b.y, 0.f), wv[i * 2 + 1], acc[j]);
            }
        }
#pragma unroll
        for (int off = 4; off >= 1; off >>= 1)
#pragma unroll
            for (int j = 0; j < 4; j++)
                acc[j] += __shfl_down_sync(0xffffffffu, acc[j], off, 8);

        if (sub == 0) {
#pragma unroll
            for (int j = 0; j < 4; j++) {
                int e = k * 128 + grp + 32 * j;
                if (e < E) out[e] = acc[j];
            }
        }
        buf ^= 1;
    }
}

// ===========================================================================
extern "C" void kernel_launch(void* const* d_in, const int* in_sizes, int n_in,
                              void* d_out, int out_size)
{
    const float*        emb = (const float*)d_in[0];
    const unsigned int* ts  = (const unsigned int*)d_in[1];
    const float*        w1  = (const float*)d_in[2];
    const float*        b1  = (const float*)d_in[3];
    const float*        w2  = (const float*)d_in[4];
    float*              out = (float*)d_out;

    int M = in_sizes[0] / D_FEAT;
    int E = in_sizes[1] / 2;

    int nchunks = (E + 127) / 128;
    int egrid = 592;                       // 4 blocks/SM, single wave
    if (egrid > nchunks) egrid = nchunks;

    cudaFuncSetAttribute(precompute_kernel,
                         cudaFuncAttributeMaxDynamicSharedMemorySize, SMEM_GEMM_TOTAL);

    // --- kernel 0: plain launch ---
    setup_w_kernel<<<32, 256>>>(w1);

    // --- kernel 1: PDL launch (overlaps with setup_w until pdl_wait) ---
    {
        cudaLaunchConfig_t cfg = {};
        cfg.gridDim  = dim3((M + 63) / 64, 1, 1);
        cfg.blockDim = dim3(256, 1, 1);
        cfg.dynamicSmemBytes = SMEM_GEMM_TOTAL;
        cudaLaunchAttribute attrs[1];
        attrs[0].id = cudaLaunchAttributeProgrammaticStreamSerialization;
        attrs[0].val.programmaticStreamSerializationAllowed = 1;
        cfg.attrs = attrs;
        cfg.numAttrs = 1;
        cudaLaunchKernelEx(&cfg, precompute_kernel, emb, b1, M);
    }

    // --- kernel 2: PDL launch (index staging overlaps precompute tail) ---
    {
        cudaLaunchConfig_t cfg = {};
        cfg.gridDim  = dim3(egrid, 1, 1);
        cfg.blockDim = dim3(256, 1, 1);
        cudaLaunchAttribute attrs[1];
        attrs[0].id = cudaLaunchAttributeProgrammaticStreamSerialization;
        attrs[0].val.programmaticStreamSerializationAllowed = 1;
        cfg.attrs = attrs;
        cfg.numAttrs = 1;
        cudaLaunchKernelEx(&cfg, edge_kernel, ts, w2, out, E, M, nchunks);
    }
}